// round 2
// baseline (speedup 1.0000x reference)
#include <cuda_runtime.h>
#include <math.h>

#define BATCH 2
#define LSEQ  2048
#define EDIM  1024
#define NLAY  2
#define DI    2048
#define DS    16
#define DC    4
#define DTR   64
#define MROWS (BATCH*LSEQ)          /* 4096 */
#define XW_ROWS (DTR + 2*DS)        /* 96 */

/* ---------------- scratch (static device globals; no allocation) ------- */
__device__ float g_h    [MROWS*EDIM];      // residual stream (B,L,E)
__device__ float g_xz   [MROWS*2*DI];      // in_proj output: [xc_raw | z]
__device__ float g_xconv[MROWS*DI];        // silu(conv(xc)+b)
__device__ float g_xdbl [MROWS*XW_ROWS];   // [dt(64) | Bm(16) | C(16)]
__device__ float g_delta[MROWS*DI];        // softplus(dt@dtw + dtb)
__device__ float g_y    [MROWS*DI];        // gated ssm output
__device__ float g_tmp  [MROWS*EDIM];      // out_proj output

/* ---------------- double-buffered SGEMM: C(M,N) = A(M,K) * W(N,K)^T ---- */
/* M % 128 == 0 and K % 16 == 0 always hold here; only N is guarded.
   mode 1 fuses v = softplus(v + bias[n]) into the epilogue. */
#define BM 128
#define BN 128
#define BKK 16

__global__ __launch_bounds__(256)
void sgemm_kernel(const float* __restrict__ A, const float* __restrict__ W,
                  float* __restrict__ C, int M, int N, int K, int lda, int ldc,
                  const float* __restrict__ bias, int mode)
{
    __shared__ float As[2][BKK][BM];
    __shared__ float Ws[2][BKK][BN];

    const int m0  = blockIdx.y * BM;
    const int n0  = blockIdx.x * BN;
    const int tid = threadIdx.x;
    const int ty  = tid >> 4;          // 0..15
    const int tx  = tid & 15;          // 0..15

    /* per-thread staging: 2 float4 of A, 2 of W per K-tile */
    const int r0 = (tid * 2)     >> 2;          // row for i=0
    const int q0 = ((tid * 2)     & 3) << 2;    // k-quad for i=0
    const int r1 = (tid * 2 + 1) >> 2;
    const int q1 = ((tid * 2 + 1) & 3) << 2;

    float4 av0, av1, wv0, wv1;

    float acc[8][8];
#pragma unroll
    for (int i = 0; i < 8; i++)
#pragma unroll
        for (int j = 0; j < 8; j++) acc[i][j] = 0.f;

    const int nt = K / BKK;

    /* prologue: fetch tile 0 */
    {
        const int k0 = 0;
        av0 = *(const float4*)(A + (size_t)(m0 + r0) * lda + k0 + q0);
        av1 = *(const float4*)(A + (size_t)(m0 + r1) * lda + k0 + q1);
        wv0 = make_float4(0.f, 0.f, 0.f, 0.f);
        wv1 = make_float4(0.f, 0.f, 0.f, 0.f);
        if (n0 + r0 < N) wv0 = *(const float4*)(W + (size_t)(n0 + r0) * K + k0 + q0);
        if (n0 + r1 < N) wv1 = *(const float4*)(W + (size_t)(n0 + r1) * K + k0 + q1);
        As[0][q0 + 0][r0] = av0.x; As[0][q0 + 1][r0] = av0.y;
        As[0][q0 + 2][r0] = av0.z; As[0][q0 + 3][r0] = av0.w;
        As[0][q1 + 0][r1] = av1.x; As[0][q1 + 1][r1] = av1.y;
        As[0][q1 + 2][r1] = av1.z; As[0][q1 + 3][r1] = av1.w;
        Ws[0][q0 + 0][r0] = wv0.x; Ws[0][q0 + 1][r0] = wv0.y;
        Ws[0][q0 + 2][r0] = wv0.z; Ws[0][q0 + 3][r0] = wv0.w;
        Ws[0][q1 + 0][r1] = wv1.x; Ws[0][q1 + 1][r1] = wv1.y;
        Ws[0][q1 + 2][r1] = wv1.z; Ws[0][q1 + 3][r1] = wv1.w;
    }
    __syncthreads();

    for (int t = 0; t < nt; t++) {
        const int cur = t & 1;
        const int nxt = cur ^ 1;

        /* issue global loads for tile t+1 (in flight during compute) */
        if (t + 1 < nt) {
            const int k0 = (t + 1) * BKK;
            av0 = *(const float4*)(A + (size_t)(m0 + r0) * lda + k0 + q0);
            av1 = *(const float4*)(A + (size_t)(m0 + r1) * lda + k0 + q1);
            wv0 = make_float4(0.f, 0.f, 0.f, 0.f);
            wv1 = make_float4(0.f, 0.f, 0.f, 0.f);
            if (n0 + r0 < N) wv0 = *(const float4*)(W + (size_t)(n0 + r0) * K + k0 + q0);
            if (n0 + r1 < N) wv1 = *(const float4*)(W + (size_t)(n0 + r1) * K + k0 + q1);
        }

        /* compute on current buffer */
#pragma unroll
        for (int kk = 0; kk < BKK; kk++) {
            float a[8], b[8];
#pragma unroll
            for (int i = 0; i < 8; i++) a[i] = As[cur][kk][ty * 8 + i];
#pragma unroll
            for (int j = 0; j < 8; j++) b[j] = Ws[cur][kk][tx * 8 + j];
#pragma unroll
            for (int i = 0; i < 8; i++)
#pragma unroll
                for (int j = 0; j < 8; j++)
                    acc[i][j] = fmaf(a[i], b[j], acc[i][j]);
        }

        /* stage tile t+1 into the other buffer (no hazard with readers) */
        if (t + 1 < nt) {
            As[nxt][q0 + 0][r0] = av0.x; As[nxt][q0 + 1][r0] = av0.y;
            As[nxt][q0 + 2][r0] = av0.z; As[nxt][q0 + 3][r0] = av0.w;
            As[nxt][q1 + 0][r1] = av1.x; As[nxt][q1 + 1][r1] = av1.y;
            As[nxt][q1 + 2][r1] = av1.z; As[nxt][q1 + 3][r1] = av1.w;
            Ws[nxt][q0 + 0][r0] = wv0.x; Ws[nxt][q0 + 1][r0] = wv0.y;
            Ws[nxt][q0 + 2][r0] = wv0.z; Ws[nxt][q0 + 3][r0] = wv0.w;
            Ws[nxt][q1 + 0][r1] = wv1.x; Ws[nxt][q1 + 1][r1] = wv1.y;
            Ws[nxt][q1 + 2][r1] = wv1.z; Ws[nxt][q1 + 3][r1] = wv1.w;
        }
        __syncthreads();
    }

#pragma unroll
    for (int i = 0; i < 8; i++) {
        size_t crow = (size_t)(m0 + ty * 8 + i) * ldc;
#pragma unroll
        for (int j4 = 0; j4 < 8; j4 += 4) {
            int n = n0 + tx * 8 + j4;
            if (n < N) {                      // N is always a multiple of 4
                float4 v;
                float* pv = &v.x;
#pragma unroll
                for (int j = 0; j < 4; j++) {
                    float a = acc[i][j4 + j];
                    if (mode == 1) {
                        a += bias[n + j];
                        a = (a > 20.f) ? a : log1pf(__expf(a));
                    }
                    pv[j] = a;
                }
                *(float4*)(C + crow + n) = v;
            }
        }
    }
}

/* ---------------- h = x + pos_embed ------------------------------------ */
__global__ void addpos_kernel(const float* __restrict__ x,
                              const float* __restrict__ pe)
{
    int idx = blockIdx.x * blockDim.x + threadIdx.x;
    if (idx >= MROWS * EDIM) return;
    int e = idx % EDIM;
    int m = idx / EDIM;
    int l = m % LSEQ;
    g_h[idx] = x[idx] + pe[l * EDIM + e];
}

/* ---------------- causal depthwise conv1d + bias + silu ---------------- */
__global__ void conv_silu_kernel(const float* __restrict__ cw,
                                 const float* __restrict__ cb)
{
    int idx = blockIdx.x * blockDim.x + threadIdx.x;
    if (idx >= MROWS * DI) return;
    int d = idx % DI;
    int m = idx / DI;
    int l = m % LSEQ;
    size_t base = (size_t)(m - l) * (2 * DI) + d;   // (b*L)*4096 + d, xc part
    float acc = cb[d];
#pragma unroll
    for (int k = 0; k < DC; k++) {
        int ll = l + k - (DC - 1);
        if (ll >= 0)
            acc = fmaf(cw[d * DC + k], g_xz[base + (size_t)ll * (2 * DI)], acc);
    }
    g_xconv[idx] = acc / (1.f + __expf(-acc));      // silu
}

/* ---------------- selective scan: 16 lanes per (b,d) channel ----------- */
__global__ __launch_bounds__(256)
void scan_kernel(const float* __restrict__ A_log,
                 const float* __restrict__ D_skip)
{
    int t  = blockIdx.x * blockDim.x + threadIdx.x;
    int ch = t >> 4;                 // channel = b*DI + d
    int n  = t & 15;                 // state index
    if (ch >= BATCH * DI) return;
    int b = ch / DI;
    int d = ch % DI;

    const float An = -__expf(A_log[d * DS + n]);
    const float Dd = D_skip[d];

    const float* dp = g_delta + (size_t)b * LSEQ * DI + d;
    const float* up = g_xconv + (size_t)b * LSEQ * DI + d;
    const float* zp = g_xz    + (size_t)b * LSEQ * (2 * DI) + DI + d;
    const float* bp = g_xdbl  + (size_t)b * LSEQ * XW_ROWS + DTR + n;
    const float* cp = bp + DS;
    float*       yp = g_y     + (size_t)b * LSEQ * DI + d;

    float h = 0.f;
    /* unroll x2: loads for the second step issue while the first step's
       recurrence chain retires (MLP=2 on the serial path) */
    for (int l = 0; l < LSEQ; l += 2) {
        float dl0 = dp[(size_t)l * DI];
        float ul0 = up[(size_t)l * DI];
        float bn0 = bp[l * XW_ROWS];
        float cn0 = cp[l * XW_ROWS];
        float dl1 = dp[(size_t)(l + 1) * DI];
        float ul1 = up[(size_t)(l + 1) * DI];
        float bn1 = bp[(l + 1) * XW_ROWS];
        float cn1 = cp[(l + 1) * XW_ROWS];

        float e0 = __expf(dl0 * An);
        float e1 = __expf(dl1 * An);

        h = fmaf(e0, h, dl0 * ul0 * bn0);
        float p0 = h * cn0;
        h = fmaf(e1, h, dl1 * ul1 * bn1);
        float p1 = h * cn1;

        p0 += __shfl_xor_sync(0xffffffffu, p0, 1);
        p1 += __shfl_xor_sync(0xffffffffu, p1, 1);
        p0 += __shfl_xor_sync(0xffffffffu, p0, 2);
        p1 += __shfl_xor_sync(0xffffffffu, p1, 2);
        p0 += __shfl_xor_sync(0xffffffffu, p0, 4);
        p1 += __shfl_xor_sync(0xffffffffu, p1, 4);
        p0 += __shfl_xor_sync(0xffffffffu, p0, 8);
        p1 += __shfl_xor_sync(0xffffffffu, p1, 8);

        if (n == 0) {
            float zl0 = zp[(size_t)l * (2 * DI)];
            float zl1 = zp[(size_t)(l + 1) * (2 * DI)];
            yp[(size_t)l * DI] =
                (p0 + ul0 * Dd) * (zl0 / (1.f + __expf(-zl0)));
            yp[(size_t)(l + 1) * DI] =
                (p1 + ul1 * Dd) * (zl1 / (1.f + __expf(-zl1)));
        }
    }
}

/* ---------------- rmsnorm(t + hin) * w --------------------------------- */
__global__ __launch_bounds__(256)
void rmsnorm_kernel(const float* __restrict__ t, const float* __restrict__ hin,
                    const float* __restrict__ w, float* __restrict__ out)
{
    __shared__ float buf[EDIM];
    __shared__ float red[8];
    int m   = blockIdx.x;
    int tid = threadIdx.x;
    float ss = 0.f;
    for (int e = tid; e < EDIM; e += 256) {
        float v = t[(size_t)m * EDIM + e] + hin[(size_t)m * EDIM + e];
        buf[e] = v;
        ss += v * v;
    }
#pragma unroll
    for (int o = 16; o; o >>= 1) ss += __shfl_xor_sync(0xffffffffu, ss, o);
    if ((tid & 31) == 0) red[tid >> 5] = ss;
    __syncthreads();
    if (tid < 32) {
        float v = (tid < 8) ? red[tid] : 0.f;
#pragma unroll
        for (int o = 4; o; o >>= 1) v += __shfl_xor_sync(0xffffffffu, v, o);
        if (tid == 0) red[0] = v;
    }
    __syncthreads();
    float scale = rsqrtf(red[0] / EDIM + 1e-6f);
    for (int e = tid; e < EDIM; e += 256)
        out[(size_t)m * EDIM + e] = buf[e] * scale * w[e];
}

/* ---------------- host driver ------------------------------------------ */
extern "C" void kernel_launch(void* const* d_in, const int* in_sizes, int n_in,
                              void* d_out, int out_size)
{
    const float* x    = (const float*)d_in[0];
    const float* pe   = (const float*)d_in[1];
    const float* inw  = (const float*)d_in[2];
    const float* cw   = (const float*)d_in[3];
    const float* cb   = (const float*)d_in[4];
    const float* xw   = (const float*)d_in[5];
    const float* dtw  = (const float*)d_in[6];
    const float* dtb  = (const float*)d_in[7];
    const float* alog = (const float*)d_in[8];
    const float* dsk  = (const float*)d_in[9];
    const float* ow   = (const float*)d_in[10];
    const float* nw   = (const float*)d_in[11];
    float* out        = (float*)d_out;

    float *ph, *pxz, *pxconv, *pxdbl, *pdelta, *py, *ptmp;
    cudaGetSymbolAddress((void**)&ph,     g_h);
    cudaGetSymbolAddress((void**)&pxz,    g_xz);
    cudaGetSymbolAddress((void**)&pxconv, g_xconv);
    cudaGetSymbolAddress((void**)&pxdbl,  g_xdbl);
    cudaGetSymbolAddress((void**)&pdelta, g_delta);
    cudaGetSymbolAddress((void**)&py,     g_y);
    cudaGetSymbolAddress((void**)&ptmp,   g_tmp);

    addpos_kernel<<<(MROWS * EDIM + 255) / 256, 256>>>(x, pe);

    for (int layer = 0; layer < NLAY; layer++) {
        const float* inw_l = inw  + (size_t)layer * (2 * DI) * EDIM;
        const float* cw_l  = cw   + (size_t)layer * DI * DC;
        const float* cb_l  = cb   + (size_t)layer * DI;
        const float* xw_l  = xw   + (size_t)layer * XW_ROWS * DI;
        const float* dtw_l = dtw  + (size_t)layer * DI * DTR;
        const float* dtb_l = dtb  + (size_t)layer * DI;
        const float* al_l  = alog + (size_t)layer * DI * DS;
        const float* ds_l  = dsk  + (size_t)layer * DI;
        const float* ow_l  = ow   + (size_t)layer * EDIM * DI;
        const float* nw_l  = nw   + (size_t)layer * EDIM;

        /* xz = h @ in_proj^T : (4096 x 4096), K=1024 */
        sgemm_kernel<<<dim3((2 * DI) / BN, MROWS / BM), 256>>>(
            ph, inw_l, pxz, MROWS, 2 * DI, EDIM, EDIM, 2 * DI, nullptr, 0);

        /* silu(conv(xc) + b) */
        conv_silu_kernel<<<(MROWS * DI + 255) / 256, 256>>>(cw_l, cb_l);

        /* x_dbl = xconv @ x_proj^T : (4096 x 96), K=2048 */
        sgemm_kernel<<<dim3(1, MROWS / BM), 256>>>(
            pxconv, xw_l, pxdbl, MROWS, XW_ROWS, DI, DI, XW_ROWS, nullptr, 0);

        /* delta = softplus(dt @ dt_proj^T + dtb) : (4096 x 2048), K=64 */
        sgemm_kernel<<<dim3(DI / BN, MROWS / BM), 256>>>(
            pxdbl, dtw_l, pdelta, MROWS, DI, DTR, XW_ROWS, DI, dtb_l, 1);

        /* selective scan + D-skip + silu(z) gate -> g_y */
        scan_kernel<<<(BATCH * DI * 16) / 256, 256>>>(al_l, ds_l);

        /* out = y @ out_proj^T : (4096 x 1024), K=2048 */
        sgemm_kernel<<<dim3(EDIM / BN, MROWS / BM), 256>>>(
            py, ow_l, ptmp, MROWS, EDIM, DI, DI, EDIM, nullptr, 0);

        /* h = rmsnorm(out + h) * w  (last layer writes d_out) */
        rmsnorm_kernel<<<MROWS, 256>>>(
            ptmp, ph, nw_l, (layer == NLAY - 1) ? out : ph);
    }
}

// round 14
// speedup vs baseline: 2.2959x; 2.2959x over previous
#include <cuda_runtime.h>
#include <cuda_bf16.h>
#include <math.h>
#include <stdint.h>

#define BATCH 2
#define LSEQ  2048
#define EDIM  1024
#define NLAY  2
#define DI    2048
#define DS    16
#define DC    4
#define DTR   64
#define MROWS (BATCH*LSEQ)          /* 4096 */
#define XW_ROWS (DTR + 2*DS)        /* 96 */

/* ---------------- scratch (static device globals; no allocation) ------- */
__device__ float g_h    [MROWS*EDIM];
__device__ float g_xz   [MROWS*2*DI];
__device__ float g_xconv[MROWS*DI];
__device__ float g_xdbl [MROWS*XW_ROWS];
__device__ float g_delta[MROWS*DI];
__device__ float g_y    [MROWS*DI];
__device__ float g_tmp  [MROWS*EDIM];
/* bf16 split operand buffers */
__device__ __nv_bfloat16 g_ah[MROWS*DI];
__device__ __nv_bfloat16 g_al[MROWS*DI];
__device__ __nv_bfloat16 g_wh[(2*DI)*EDIM];
__device__ __nv_bfloat16 g_wl[(2*DI)*EDIM];

/* ================= baseline-PTX helpers (sm_80 features only) ========== */
__device__ __forceinline__ uint32_t smem_u32(const void* p) {
    uint32_t a;
    asm("{ .reg .u64 t; cvta.to.shared.u64 t, %1; cvt.u32.u64 %0, t; }"
        : "=r"(a) : "l"(p));
    return a;
}
__device__ __forceinline__ void cp_async16(uint32_t saddr, const void* gaddr) {
    asm volatile("cp.async.cg.shared.global [%0], [%1], 16;"
                 :: "r"(saddr), "l"(gaddr) : "memory");
}
__device__ __forceinline__ void cp_commit() {
    asm volatile("cp.async.commit_group;" ::: "memory");
}
template <int N> __device__ __forceinline__ void cp_wait() {
    asm volatile("cp.async.wait_group %0;" :: "n"(N) : "memory");
}
__device__ __forceinline__ void ldm_x4(uint32_t* d, uint32_t addr) {
    asm volatile("ldmatrix.sync.aligned.m8n8.x4.shared.b16 {%0,%1,%2,%3}, [%4];"
                 : "=r"(d[0]), "=r"(d[1]), "=r"(d[2]), "=r"(d[3]) : "r"(addr));
}
__device__ __forceinline__ void mma16816(float* c, const uint32_t* a, const uint32_t* b) {
    asm volatile("mma.sync.aligned.m16n8k16.row.col.f32.bf16.bf16.f32 "
                 "{%0,%1,%2,%3}, {%4,%5,%6,%7}, {%8,%9}, {%0,%1,%2,%3};"
                 : "+f"(c[0]), "+f"(c[1]), "+f"(c[2]), "+f"(c[3])
                 : "r"(a[0]), "r"(a[1]), "r"(a[2]), "r"(a[3]),
                   "r"(b[0]), "r"(b[1]));
}

/* ================= split-bf16 GEMM via mma.sync ======================== */
/* C(M,N) = A(M,K) * W(N,K)^T ~= Ah*Wh^T + Ah*Wl^T + Al*Wh^T, fp32 accum.
   CTA: 128x128 tile, BK=64, 256 thr (8 warps, 2x4), warp tile 64x32.
   Smem: 4 operand tiles (128 rows x 128B, XOR-swizzled) x 2 stages = 128KB.
   W buffer always has >= n0+128 rows (x_proj weight padded to 128).
   mode 1: fuse softplus(v + bias[n]). */
#define STG   65536
#define AH_O  0
#define AL_O  16384
#define WH_O  32768
#define WL_O  49152
#define SMEM_BYTES (2*STG)

__global__ __launch_bounds__(256)
void tc_gemm(const __nv_bfloat16* __restrict__ Ah, const __nv_bfloat16* __restrict__ Al,
             const __nv_bfloat16* __restrict__ Wh, const __nv_bfloat16* __restrict__ Wl,
             float* __restrict__ C, int K, int N, int ldc,
             const float* __restrict__ bias, int mode)
{
    extern __shared__ char dsm[];
    const uint32_t sb  = smem_u32(dsm);
    const int tid    = threadIdx.x;
    const int lane   = tid & 31;
    const int wid    = tid >> 5;
    const int warp_m = wid >> 2;          /* 0..1 -> 64-row half  */
    const int warp_n = wid & 3;           /* 0..3 -> 32-col slice */
    const int m0 = blockIdx.y * 128;
    const int n0 = blockIdx.x * 128;

    /* ---- staging helper: tile t -> stage (t&1) ---- */
    const int nt = K >> 6;
    auto stage_tile = [&](int t) {
        const int k0   = t << 6;                  /* element offset   */
        const uint32_t s = sb + (t & 1) * STG;
#pragma unroll
        for (int i = tid; i < 1024; i += 256) {
            int r = i >> 3;
            int c = i & 7;
            uint32_t sw = (uint32_t)(r * 128 + ((c ^ (r & 7)) << 4));
            const char* ga  = (const char*)(Ah + (size_t)(m0 + r) * K + k0) + c * 16;
            const char* gal = (const char*)(Al + (size_t)(m0 + r) * K + k0) + c * 16;
            const char* gw  = (const char*)(Wh + (size_t)(n0 + r) * K + k0) + c * 16;
            const char* gwl = (const char*)(Wl + (size_t)(n0 + r) * K + k0) + c * 16;
            cp_async16(s + AH_O + sw, ga);
            cp_async16(s + AL_O + sw, gal);
            cp_async16(s + WH_O + sw, gw);
            cp_async16(s + WL_O + sw, gwl);
        }
        cp_commit();
    };

    float acc[4][4][4];
#pragma unroll
    for (int i = 0; i < 4; i++)
#pragma unroll
        for (int j = 0; j < 4; j++)
#pragma unroll
            for (int e = 0; e < 4; e++) acc[i][j][e] = 0.f;

    stage_tile(0);

    for (int t = 0; t < nt; t++) {
        if (t + 1 < nt) { stage_tile(t + 1); cp_wait<1>(); }
        else            { cp_wait<0>(); }
        __syncthreads();

        const uint32_t s = sb + (t & 1) * STG;

        /* A-fragment ldmatrix address (same formula for Ah/Al):
           rows = warp_m*64 + mt*16 + (lane&15), k-half = lane>>4 */
        const int arow = warp_m * 64 + (lane & 15);
        const int ahalf = lane >> 4;
        /* W-fragment x4 covers 2 n-tiles:
           rows = warp_n*32 + p*16 + (lane&7) + ((lane>>4)<<3), half=(lane>>3)&1 */
        const int wrow = warp_n * 32 + (lane & 7) + ((lane >> 4) << 3);
        const int whalf = (lane >> 3) & 1;

#pragma unroll
        for (int ks = 0; ks < 4; ks++) {
            uint32_t fah[4][4], fal[4][4], fbh[4][2], fbl[4][2];
#pragma unroll
            for (int mt = 0; mt < 4; mt++) {
                int r = arow + mt * 16;
                int c = ks * 2 + ahalf;
                uint32_t ad = (uint32_t)(r * 128 + ((c ^ (r & 7)) << 4));
                ldm_x4(fah[mt], s + AH_O + ad);
                ldm_x4(fal[mt], s + AL_O + ad);
            }
#pragma unroll
            for (int p = 0; p < 2; p++) {
                int r = wrow + p * 16;
                int c = ks * 2 + whalf;
                uint32_t ad = (uint32_t)(r * 128 + ((c ^ (r & 7)) << 4));
                uint32_t th[4], tl[4];
                ldm_x4(th, s + WH_O + ad);
                ldm_x4(tl, s + WL_O + ad);
                fbh[2*p][0] = th[0]; fbh[2*p][1] = th[1];
                fbh[2*p+1][0] = th[2]; fbh[2*p+1][1] = th[3];
                fbl[2*p][0] = tl[0]; fbl[2*p][1] = tl[1];
                fbl[2*p+1][0] = tl[2]; fbl[2*p+1][1] = tl[3];
            }
#pragma unroll
            for (int mt = 0; mt < 4; mt++)
#pragma unroll
                for (int ntt = 0; ntt < 4; ntt++) {
                    mma16816(acc[mt][ntt], fah[mt], fbh[ntt]);
                    mma16816(acc[mt][ntt], fah[mt], fbl[ntt]);
                    mma16816(acc[mt][ntt], fal[mt], fbh[ntt]);
                }
        }
        __syncthreads();
    }

    /* ---- epilogue: acc -> C (optionally softplus(v+bias)) ---- */
#pragma unroll
    for (int mt = 0; mt < 4; mt++) {
#pragma unroll
        for (int ntt = 0; ntt < 4; ntt++) {
            int row = m0 + warp_m * 64 + mt * 16 + (lane >> 2);
            int col = n0 + warp_n * 32 + ntt * 8 + ((lane & 3) << 1);
            if (col < N) {
                float v0 = acc[mt][ntt][0], v1 = acc[mt][ntt][1];
                float v2 = acc[mt][ntt][2], v3 = acc[mt][ntt][3];
                if (mode == 1) {
                    float b0 = bias[col], b1 = bias[col + 1];
                    v0 += b0; v1 += b1; v2 += b0; v3 += b1;
                    v0 = (v0 > 20.f) ? v0 : log1pf(__expf(v0));
                    v1 = (v1 > 20.f) ? v1 : log1pf(__expf(v1));
                    v2 = (v2 > 20.f) ? v2 : log1pf(__expf(v2));
                    v3 = (v3 > 20.f) ? v3 : log1pf(__expf(v3));
                }
                *(float2*)(C + (size_t)row * ldc + col)       = make_float2(v0, v1);
                *(float2*)(C + (size_t)(row + 8) * ldc + col) = make_float2(v2, v3);
            }
        }
    }
}

/* ---------------- fp32 -> bf16 hi/lo split (with pad + stride) --------- */
__global__ void split_bf16_kernel(const float* __restrict__ src,
                                  __nv_bfloat16* __restrict__ hi,
                                  __nv_bfloat16* __restrict__ lo,
                                  int dst_rows, int cols, int src_rows, int src_stride)
{
    int idx = blockIdx.x * blockDim.x + threadIdx.x;
    if (idx >= dst_rows * cols) return;
    int r = idx / cols;
    int c = idx - r * cols;
    float v = (r < src_rows) ? src[(size_t)r * src_stride + c] : 0.f;
    __nv_bfloat16 h = __float2bfloat16(v);
    hi[idx] = h;
    lo[idx] = __float2bfloat16(v - __bfloat162float(h));
}

/* ---------------- h = x + pos_embed ------------------------------------ */
__global__ void addpos_kernel(const float* __restrict__ x,
                              const float* __restrict__ pe)
{
    int idx = blockIdx.x * blockDim.x + threadIdx.x;
    if (idx >= MROWS * EDIM) return;
    int e = idx % EDIM;
    int m = idx / EDIM;
    int l = m % LSEQ;
    g_h[idx] = x[idx] + pe[l * EDIM + e];
}

/* ---------------- causal depthwise conv1d + bias + silu ---------------- */
__global__ void conv_silu_kernel(const float* __restrict__ cw,
                                 const float* __restrict__ cb)
{
    int idx = blockIdx.x * blockDim.x + threadIdx.x;
    if (idx >= MROWS * DI) return;
    int d = idx % DI;
    int m = idx / DI;
    int l = m % LSEQ;
    size_t base = (size_t)(m - l) * (2 * DI) + d;
    float acc = cb[d];
#pragma unroll
    for (int k = 0; k < DC; k++) {
        int ll = l + k - (DC - 1);
        if (ll >= 0)
            acc = fmaf(cw[d * DC + k], g_xz[base + (size_t)ll * (2 * DI)], acc);
    }
    g_xconv[idx] = acc / (1.f + __expf(-acc));
}

/* ---------------- selective scan: 16 lanes per (b,d) channel ----------- */
__global__ __launch_bounds__(256)
void scan_kernel(const float* __restrict__ A_log,
                 const float* __restrict__ D_skip)
{
    int t  = blockIdx.x * blockDim.x + threadIdx.x;
    int ch = t >> 4;
    int n  = t & 15;
    if (ch >= BATCH * DI) return;
    int b = ch / DI;
    int d = ch % DI;

    const float An = -__expf(A_log[d * DS + n]);
    const float Dd = D_skip[d];

    const float* dp = g_delta + (size_t)b * LSEQ * DI + d;
    const float* up = g_xconv + (size_t)b * LSEQ * DI + d;
    const float* zp = g_xz    + (size_t)b * LSEQ * (2 * DI) + DI + d;
    const float* bp = g_xdbl  + (size_t)b * LSEQ * XW_ROWS + DTR + n;
    const float* cp = bp + DS;
    float*       yp = g_y     + (size_t)b * LSEQ * DI + d;

    float h = 0.f;
    for (int l = 0; l < LSEQ; l += 2) {
        float dl0 = dp[(size_t)l * DI];
        float ul0 = up[(size_t)l * DI];
        float bn0 = bp[l * XW_ROWS];
        float cn0 = cp[l * XW_ROWS];
        float dl1 = dp[(size_t)(l + 1) * DI];
        float ul1 = up[(size_t)(l + 1) * DI];
        float bn1 = bp[(l + 1) * XW_ROWS];
        float cn1 = cp[(l + 1) * XW_ROWS];

        float e0 = __expf(dl0 * An);
        float e1 = __expf(dl1 * An);

        h = fmaf(e0, h, dl0 * ul0 * bn0);
        float p0 = h * cn0;
        h = fmaf(e1, h, dl1 * ul1 * bn1);
        float p1 = h * cn1;

        p0 += __shfl_xor_sync(0xffffffffu, p0, 1);
        p1 += __shfl_xor_sync(0xffffffffu, p1, 1);
        p0 += __shfl_xor_sync(0xffffffffu, p0, 2);
        p1 += __shfl_xor_sync(0xffffffffu, p1, 2);
        p0 += __shfl_xor_sync(0xffffffffu, p0, 4);
        p1 += __shfl_xor_sync(0xffffffffu, p1, 4);
        p0 += __shfl_xor_sync(0xffffffffu, p0, 8);
        p1 += __shfl_xor_sync(0xffffffffu, p1, 8);

        if (n == 0) {
            float zl0 = zp[(size_t)l * (2 * DI)];
            float zl1 = zp[(size_t)(l + 1) * (2 * DI)];
            yp[(size_t)l * DI] =
                (p0 + ul0 * Dd) * (zl0 / (1.f + __expf(-zl0)));
            yp[(size_t)(l + 1) * DI] =
                (p1 + ul1 * Dd) * (zl1 / (1.f + __expf(-zl1)));
        }
    }
}

/* ---------------- rmsnorm(t + hin) * w --------------------------------- */
__global__ __launch_bounds__(256)
void rmsnorm_kernel(const float* __restrict__ t, const float* __restrict__ hin,
                    const float* __restrict__ w, float* __restrict__ out)
{
    __shared__ float buf[EDIM];
    __shared__ float red[8];
    int m   = blockIdx.x;
    int tid = threadIdx.x;
    float ss = 0.f;
    for (int e = tid; e < EDIM; e += 256) {
        float v = t[(size_t)m * EDIM + e] + hin[(size_t)m * EDIM + e];
        buf[e] = v;
        ss += v * v;
    }
#pragma unroll
    for (int o = 16; o; o >>= 1) ss += __shfl_xor_sync(0xffffffffu, ss, o);
    if ((tid & 31) == 0) red[tid >> 5] = ss;
    __syncthreads();
    if (tid < 32) {
        float v = (tid < 8) ? red[tid] : 0.f;
#pragma unroll
        for (int o = 4; o; o >>= 1) v += __shfl_xor_sync(0xffffffffu, v, o);
        if (tid == 0) red[0] = v;
    }
    __syncthreads();
    float scale = rsqrtf(red[0] / EDIM + 1e-6f);
    for (int e = tid; e < EDIM; e += 256)
        out[(size_t)m * EDIM + e] = buf[e] * scale * w[e];
}

/* ---------------- host driver ------------------------------------------ */
static inline void split_launch(const float* src, __nv_bfloat16* hi, __nv_bfloat16* lo,
                                int dst_rows, int cols, int src_rows, int src_stride)
{
    int n = dst_rows * cols;
    split_bf16_kernel<<<(n + 255) / 256, 256>>>(src, hi, lo, dst_rows, cols,
                                                src_rows, src_stride);
}

extern "C" void kernel_launch(void* const* d_in, const int* in_sizes, int n_in,
                              void* d_out, int out_size)
{
    const float* x    = (const float*)d_in[0];
    const float* pe   = (const float*)d_in[1];
    const float* inw  = (const float*)d_in[2];
    const float* cw   = (const float*)d_in[3];
    const float* cb   = (const float*)d_in[4];
    const float* xw   = (const float*)d_in[5];
    const float* dtw  = (const float*)d_in[6];
    const float* dtb  = (const float*)d_in[7];
    const float* alog = (const float*)d_in[8];
    const float* dsk  = (const float*)d_in[9];
    const float* ow   = (const float*)d_in[10];
    const float* nw   = (const float*)d_in[11];
    float* out        = (float*)d_out;

    cudaFuncSetAttribute(tc_gemm, cudaFuncAttributeMaxDynamicSharedMemorySize,
                         SMEM_BYTES);

    float *ph, *pxz, *pxconv, *pxdbl, *pdelta, *py, *ptmp;
    __nv_bfloat16 *pah, *pal, *pwh, *pwl;
    cudaGetSymbolAddress((void**)&ph,     g_h);
    cudaGetSymbolAddress((void**)&pxz,    g_xz);
    cudaGetSymbolAddress((void**)&pxconv, g_xconv);
    cudaGetSymbolAddress((void**)&pxdbl,  g_xdbl);
    cudaGetSymbolAddress((void**)&pdelta, g_delta);
    cudaGetSymbolAddress((void**)&py,     g_y);
    cudaGetSymbolAddress((void**)&ptmp,   g_tmp);
    cudaGetSymbolAddress((void**)&pah,    g_ah);
    cudaGetSymbolAddress((void**)&pal,    g_al);
    cudaGetSymbolAddress((void**)&pwh,    g_wh);
    cudaGetSymbolAddress((void**)&pwl,    g_wl);

    addpos_kernel<<<(MROWS * EDIM + 255) / 256, 256>>>(x, pe);

    for (int layer = 0; layer < NLAY; layer++) {
        const float* inw_l = inw  + (size_t)layer * (2 * DI) * EDIM;
        const float* cw_l  = cw   + (size_t)layer * DI * DC;
        const float* cb_l  = cb   + (size_t)layer * DI;
        const float* xw_l  = xw   + (size_t)layer * XW_ROWS * DI;
        const float* dtw_l = dtw  + (size_t)layer * DI * DTR;
        const float* dtb_l = dtb  + (size_t)layer * DI;
        const float* al_l  = alog + (size_t)layer * DI * DS;
        const float* ds_l  = dsk  + (size_t)layer * DI;
        const float* ow_l  = ow   + (size_t)layer * EDIM * DI;
        const float* nw_l  = nw   + (size_t)layer * EDIM;

        /* ---- in_proj: (4096 x 4096), K=1024 ---- */
        split_launch(ph,    pah, pal, MROWS,  EDIM, MROWS,  EDIM);
        split_launch(inw_l, pwh, pwl, 2 * DI, EDIM, 2 * DI, EDIM);
        tc_gemm<<<dim3((2 * DI) / 128, MROWS / 128), 256, SMEM_BYTES>>>(
            pah, pal, pwh, pwl, pxz, EDIM, 2 * DI, 2 * DI, nullptr, 0);

        conv_silu_kernel<<<(MROWS * DI + 255) / 256, 256>>>(cw_l, cb_l);

        /* ---- x_proj: (4096 x 96), K=2048, weight padded to 128 rows ---- */
        split_launch(pxconv, pah, pal, MROWS, DI, MROWS,   DI);
        split_launch(xw_l,   pwh, pwl, 128,   DI, XW_ROWS, DI);
        tc_gemm<<<dim3(1, MROWS / 128), 256, SMEM_BYTES>>>(
            pah, pal, pwh, pwl, pxdbl, DI, XW_ROWS, XW_ROWS, nullptr, 0);

        /* ---- dt_proj: (4096 x 2048), K=64, fused softplus+bias ---- */
        split_launch(pxdbl, pah, pal, MROWS, DTR, MROWS, XW_ROWS);
        split_launch(dtw_l, pwh, pwl, DI,    DTR, DI,    DTR);
        tc_gemm<<<dim3(DI / 128, MROWS / 128), 256, SMEM_BYTES>>>(
            pah, pal, pwh, pwl, pdelta, DTR, DI, DI, dtb_l, 1);

        /* ---- selective scan + D-skip + silu(z) gate ---- */
        scan_kernel<<<(BATCH * DI * 16) / 256, 256>>>(al_l, ds_l);

        /* ---- out_proj: (4096 x 1024), K=2048 ---- */
        split_launch(py,   pah, pal, MROWS, DI, MROWS, DI);
        split_launch(ow_l, pwh, pwl, EDIM,  DI, EDIM,  DI);
        tc_gemm<<<dim3(EDIM / 128, MROWS / 128), 256, SMEM_BYTES>>>(
            pah, pal, pwh, pwl, ptmp, DI, EDIM, EDIM, nullptr, 0);

        /* ---- h = rmsnorm(out + h) * w ---- */
        rmsnorm_kernel<<<MROWS, 256>>>(
            ptmp, ph, nw_l, (layer == NLAY - 1) ? out : ph);
    }
}